// round 1
// baseline (speedup 1.0000x reference)
#include <cuda_runtime.h>
#include <math.h>

#define BB 2
#define SS 8500
#define CC 512
#define HH 8
#define DD 64
#define DFFN 1024
#define MT (BB*SS)   // 17000

// ---------------- scratch (device globals; no allocations allowed) ------------
__device__ float g_q   [MT*CC];     // src+pos
__device__ float g_val [MT*CC];     // value projection
__device__ float g_off [MT*256];    // sampling offsets  [bs, h, l, p, 2]
__device__ float g_lgt [MT*128];    // attn logits       [bs, h, l*p]
__device__ float g_smp [MT*CC];     // sampled output
__device__ float g_tmp [MT*CC];     // attn_out, later ffn_out
__device__ float g_x   [MT*CC];     // post-LN1
__device__ float g_hid [MT*DFFN];   // ffn hidden

// ---------------- elementwise add (q = src + pos) ----------------------------
__global__ void add_kernel(const float* __restrict__ a, const float* __restrict__ b,
                           float* __restrict__ o, int n4) {
    int i = blockIdx.x * blockDim.x + threadIdx.x;
    if (i < n4) {
        float4 x = ((const float4*)a)[i];
        float4 y = ((const float4*)b)[i];
        ((float4*)o)[i] = make_float4(x.x + y.x, x.y + y.y, x.z + y.z, x.w + y.w);
    }
}

// ---------------- SGEMM: C[M,N] = A[M,K] @ W[K,N] + bias (opt relu) ----------
// BM=BN=128, BK=8, 256 threads, 8x8 micro-tile per thread.
template<bool RELU>
__global__ __launch_bounds__(256, 2)
void sgemm128(const float* __restrict__ A, const float* __restrict__ W,
              const float* __restrict__ bias, float* __restrict__ C,
              int M, int N, int K) {
    __shared__ __align__(16) float As[8][132];   // [k][m], padded pitch
    __shared__ __align__(16) float Ws[8][128];   // [k][n]

    const int tid = threadIdx.x;
    const int m0 = (tid >> 4) << 3;        // 0..120
    const int n0 = (tid & 15) << 3;        // 0..120
    const int mb = blockIdx.y * 128;
    const int nb = blockIdx.x * 128;

    const int arow = tid >> 1;             // 0..127
    const int ak   = (tid & 1) * 4;        // 0 or 4
    const int wrow = tid >> 5;             // 0..7
    const int wn   = (tid & 31) * 4;       // 0..124

    const bool arowok = (mb + arow) < M;
    const float* Aptr = A + (size_t)(mb + arow) * K + ak;
    const float* Wptr = W + (size_t)wrow * N + nb + wn;

    float acc[8][8];
    #pragma unroll
    for (int i = 0; i < 8; i++)
        #pragma unroll
        for (int j = 0; j < 8; j++) acc[i][j] = 0.f;

    for (int k0 = 0; k0 < K; k0 += 8) {
        float4 av = arowok ? *(const float4*)(Aptr + k0)
                           : make_float4(0.f, 0.f, 0.f, 0.f);
        As[ak + 0][arow] = av.x;
        As[ak + 1][arow] = av.y;
        As[ak + 2][arow] = av.z;
        As[ak + 3][arow] = av.w;
        *(float4*)&Ws[wrow][wn] = *(const float4*)(Wptr + (size_t)k0 * N);
        __syncthreads();

        #pragma unroll
        for (int kk = 0; kk < 8; kk++) {
            float4 a0 = *(const float4*)&As[kk][m0];
            float4 a1 = *(const float4*)&As[kk][m0 + 4];
            float4 b0 = *(const float4*)&Ws[kk][n0];
            float4 b1 = *(const float4*)&Ws[kk][n0 + 4];
            float a[8] = {a0.x, a0.y, a0.z, a0.w, a1.x, a1.y, a1.z, a1.w};
            float b[8] = {b0.x, b0.y, b0.z, b0.w, b1.x, b1.y, b1.z, b1.w};
            #pragma unroll
            for (int i = 0; i < 8; i++)
                #pragma unroll
                for (int j = 0; j < 8; j++)
                    acc[i][j] += a[i] * b[j];
        }
        __syncthreads();
    }

    float bv[8];
    #pragma unroll
    for (int j = 0; j < 8; j++) bv[j] = bias[nb + n0 + j];

    #pragma unroll
    for (int i = 0; i < 8; i++) {
        int gm = mb + m0 + i;
        if (gm < M) {
            float4 o0, o1;
            float v0 = acc[i][0] + bv[0], v1 = acc[i][1] + bv[1];
            float v2 = acc[i][2] + bv[2], v3 = acc[i][3] + bv[3];
            float v4 = acc[i][4] + bv[4], v5 = acc[i][5] + bv[5];
            float v6 = acc[i][6] + bv[6], v7 = acc[i][7] + bv[7];
            if (RELU) {
                v0 = fmaxf(v0, 0.f); v1 = fmaxf(v1, 0.f);
                v2 = fmaxf(v2, 0.f); v3 = fmaxf(v3, 0.f);
                v4 = fmaxf(v4, 0.f); v5 = fmaxf(v5, 0.f);
                v6 = fmaxf(v6, 0.f); v7 = fmaxf(v7, 0.f);
            }
            o0 = make_float4(v0, v1, v2, v3);
            o1 = make_float4(v4, v5, v6, v7);
            *(float4*)(C + (size_t)gm * N + nb + n0)     = o0;
            *(float4*)(C + (size_t)gm * N + nb + n0 + 4) = o1;
        }
    }
}

// ---------------- deformable sampling: one warp per (b,s,h) ------------------
__global__ void sample_kernel(const float* __restrict__ value,
                              const float* __restrict__ offs,
                              const float* __restrict__ logits,
                              float* __restrict__ out) {
    int gw = (blockIdx.x * blockDim.x + threadIdx.x) >> 5;
    if (gw >= MT * HH) return;
    const int lane = threadIdx.x & 31;
    const int h  = gw & 7;
    const int bs = gw >> 3;              // b*S + s
    const int s  = bs % SS;
    const int rowb = bs - s;             // b*S

    // query's level + reference point
    int lvlW, idx;
    float refx, refy;
    {
        int lvlH;
        if (s < 6400)      { lvlH = 80; lvlW = 80; idx = s; }
        else if (s < 8000) { lvlH = 40; lvlW = 40; idx = s - 6400; }
        else if (s < 8400) { lvlH = 20; lvlW = 20; idx = s - 8000; }
        else               { lvlH = 10; lvlW = 10; idx = s - 8400; }
        refx = ((idx % lvlW) + 0.5f) / (float)lvlW;
        refy = ((idx / lvlW) + 0.5f) / (float)lvlH;
    }

    // softmax over 16 attn logits (redundant per lane; broadcast loads)
    const float* lg = logits + (size_t)gw * 16;
    float w[16];
    float mx = -1e30f;
    #pragma unroll
    for (int i = 0; i < 16; i++) { w[i] = __ldg(lg + i); mx = fmaxf(mx, w[i]); }
    float sum = 0.f;
    #pragma unroll
    for (int i = 0; i < 16; i++) { w[i] = __expf(w[i] - mx); sum += w[i]; }
    const float inv = 1.0f / sum;

    const float* of = offs + (size_t)gw * 32;
    const int d0 = h * DD + lane * 2;
    float ax = 0.f, ay = 0.f;

    const int LH[4] = {80, 40, 20, 10};
    const int LW[4] = {80, 40, 20, 10};
    const int LS[4] = {0, 6400, 8000, 8400};

    #pragma unroll
    for (int l = 0; l < 4; l++) {
        const int Hh = LH[l], Ww = LW[l];
        const float* vb = value + (size_t)(rowb + LS[l]) * CC + d0;
        #pragma unroll
        for (int p = 0; p < 4; p++) {
            float ox = __ldg(of + (l * 4 + p) * 2);
            float oy = __ldg(of + (l * 4 + p) * 2 + 1);
            float aw = w[l * 4 + p] * inv;
            // loc = ref + off/(W,H); x = loc.x*W - 0.5  ==  ref.x*W + off.x - 0.5
            float x = refx * (float)Ww + ox - 0.5f;
            float y = refy * (float)Hh + oy - 0.5f;
            float xf = floorf(x), yf = floorf(y);
            int x0 = (int)xf, y0 = (int)yf;
            float fx = x - xf, fy = y - yf;
            float w00 = (1.f - fx) * (1.f - fy) * aw;
            float w01 = fx * (1.f - fy) * aw;
            float w10 = (1.f - fx) * fy * aw;
            float w11 = fx * fy * aw;
            bool xi0 = (x0 >= 0) && (x0 < Ww);
            bool xi1 = (x0 + 1 >= 0) && (x0 + 1 < Ww);
            bool yi0 = (y0 >= 0) && (y0 < Hh);
            bool yi1 = (y0 + 1 >= 0) && (y0 + 1 < Hh);
            if (xi0 && yi0) {
                float2 v = *(const float2*)(vb + (size_t)(y0 * Ww + x0) * CC);
                ax += w00 * v.x; ay += w00 * v.y;
            }
            if (xi1 && yi0) {
                float2 v = *(const float2*)(vb + (size_t)(y0 * Ww + x0 + 1) * CC);
                ax += w01 * v.x; ay += w01 * v.y;
            }
            if (xi0 && yi1) {
                float2 v = *(const float2*)(vb + (size_t)((y0 + 1) * Ww + x0) * CC);
                ax += w10 * v.x; ay += w10 * v.y;
            }
            if (xi1 && yi1) {
                float2 v = *(const float2*)(vb + (size_t)((y0 + 1) * Ww + x0 + 1) * CC);
                ax += w11 * v.x; ay += w11 * v.y;
            }
        }
    }
    *(float2*)(out + (size_t)bs * CC + d0) = make_float2(ax, ay);
}

// ---------------- fused residual + LayerNorm ---------------------------------
// out[row] = LN(a[row] + r[row]) * g + b       (C = 512, 128 threads, 4/thread)
__global__ void ln_residual(const float* __restrict__ a, const float* __restrict__ r,
                            const float* __restrict__ g, const float* __restrict__ bta,
                            float* __restrict__ out) {
    const int row = blockIdx.x;
    const int t = threadIdx.x;          // 0..127
    const float4 va = ((const float4*)(a + (size_t)row * CC))[t];
    const float4 vr = ((const float4*)(r + (size_t)row * CC))[t];
    float x0 = va.x + vr.x, x1 = va.y + vr.y, x2 = va.z + vr.z, x3 = va.w + vr.w;

    float sum = x0 + x1 + x2 + x3;
    float sq  = x0 * x0 + x1 * x1 + x2 * x2 + x3 * x3;
    #pragma unroll
    for (int o = 16; o; o >>= 1) {
        sum += __shfl_xor_sync(0xffffffffu, sum, o);
        sq  += __shfl_xor_sync(0xffffffffu, sq,  o);
    }
    __shared__ float sh[8];
    const int wid = t >> 5, lane = t & 31;
    if (lane == 0) { sh[wid] = sum; sh[wid + 4] = sq; }
    __syncthreads();
    sum = sh[0] + sh[1] + sh[2] + sh[3];
    sq  = sh[4] + sh[5] + sh[6] + sh[7];

    const float mean = sum * (1.0f / CC);
    const float var  = sq * (1.0f / CC) - mean * mean;
    const float istd = rsqrtf(var + 1e-5f);

    const float4 vg = ((const float4*)g)[t];
    const float4 vb = ((const float4*)bta)[t];
    float4 o4;
    o4.x = (x0 - mean) * istd * vg.x + vb.x;
    o4.y = (x1 - mean) * istd * vg.y + vb.y;
    o4.z = (x2 - mean) * istd * vg.z + vb.z;
    o4.w = (x3 - mean) * istd * vg.w + vb.w;
    ((float4*)(out + (size_t)row * CC))[t] = o4;
}

// ---------------- launch ------------------------------------------------------
static float* sym(const void* s) {
    void* p = nullptr;
    cudaGetSymbolAddress(&p, s);
    return (float*)p;
}

extern "C" void kernel_launch(void* const* d_in, const int* in_sizes, int n_in,
                              void* d_out, int out_size) {
    const float* src    = (const float*)d_in[0];
    const float* pos    = (const float*)d_in[1];
    const float* w_off  = (const float*)d_in[2];
    const float* b_off  = (const float*)d_in[3];
    const float* w_attn = (const float*)d_in[4];
    const float* b_attn = (const float*)d_in[5];
    const float* w_val  = (const float*)d_in[6];
    const float* b_val  = (const float*)d_in[7];
    const float* w_out  = (const float*)d_in[8];
    const float* b_out  = (const float*)d_in[9];
    const float* ln1_g  = (const float*)d_in[10];
    const float* ln1_b  = (const float*)d_in[11];
    const float* w1     = (const float*)d_in[12];
    const float* b1     = (const float*)d_in[13];
    const float* w2     = (const float*)d_in[14];
    const float* b2     = (const float*)d_in[15];
    const float* ln2_g  = (const float*)d_in[16];
    const float* ln2_b  = (const float*)d_in[17];
    float* out = (float*)d_out;

    float* q    = sym(g_q);
    float* val  = sym(g_val);
    float* off  = sym(g_off);
    float* lgt  = sym(g_lgt);
    float* smp  = sym(g_smp);
    float* tmp  = sym(g_tmp);
    float* x    = sym(g_x);
    float* hid  = sym(g_hid);

    const int M = MT;
    const int mblocks = (M + 127) / 128;

    // 1. q = src + pos
    {
        int n4 = MT * CC / 4;
        add_kernel<<<(n4 + 255) / 256, 256>>>(src, pos, q, n4);
    }
    // 2. value = src @ w_val + b_val        [17000,512]x[512,512]
    sgemm128<false><<<dim3(CC / 128, mblocks), 256>>>(src, w_val, b_val, val, M, CC, CC);
    // 3. offsets = q @ w_off + b_off        [17000,512]x[512,256]
    sgemm128<false><<<dim3(256 / 128, mblocks), 256>>>(q, w_off, b_off, off, M, 256, CC);
    // 4. logits = q @ w_attn + b_attn       [17000,512]x[512,128]
    sgemm128<false><<<dim3(128 / 128, mblocks), 256>>>(q, w_attn, b_attn, lgt, M, 128, CC);
    // 5. deformable sampling
    {
        int warps = MT * HH;                       // 136000
        int blocks = (warps * 32 + 255) / 256;     // 17000
        sample_kernel<<<blocks, 256>>>(val, off, lgt, smp);
    }
    // 6. attn_out = smp @ w_out + b_out
    sgemm128<false><<<dim3(CC / 128, mblocks), 256>>>(smp, w_out, b_out, tmp, M, CC, CC);
    // 7. x = LN(src + attn_out)
    ln_residual<<<MT, 128>>>(src, tmp, ln1_g, ln1_b, x);
    // 8. hid = relu(x @ w1 + b1)            [17000,512]x[512,1024]
    sgemm128<true><<<dim3(DFFN / 128, mblocks), 256>>>(x, w1, b1, hid, M, DFFN, CC);
    // 9. ffn = hid @ w2 + b2                [17000,1024]x[1024,512]
    sgemm128<false><<<dim3(CC / 128, mblocks), 256>>>(hid, w2, b2, tmp, M, CC, DFFN);
    // 10. out = LN(x + ffn)
    ln_residual<<<MT, 128>>>(x, tmp, ln2_g, ln2_b, out);
}

// round 3
// speedup vs baseline: 3.9968x; 3.9968x over previous
#include <cuda_runtime.h>
#include <math.h>
#include <stdint.h>

#define BB 2
#define SS 8500
#define CC 512
#define HH 8
#define DD 64
#define DFFN 1024
#define MT (BB*SS)   // 17000

// smem pitches (floats) — chosen for conflict-free mma fragment LDS
#define PA 36        // A tile pitch: bank(4g+t) unique over a fragment
#define PB 136       // B tile pitch: bank(8t+4c) unique per STS/LDS phase
#define ABUF (128*PA)
#define BBUF (32*PB)
#define SMEM_FLOATS (2*ABUF + 2*BBUF)

// ---------------- scratch (device globals; no allocations allowed) ------------
__device__ float g_q   [MT*CC];
__device__ float g_val [MT*CC];
__device__ float g_off [MT*256];
__device__ float g_lgt [MT*128];
__device__ float g_smp [MT*CC];
__device__ float g_tmp [MT*CC];
__device__ float g_x   [MT*CC];
__device__ float g_hid [MT*DFFN];

__device__ __forceinline__ uint32_t smem_u32(const void* p) {
    return (uint32_t)__cvta_generic_to_shared(p);
}

__device__ __forceinline__ void mma_tf32(float* d, const uint32_t* a, const uint32_t* b) {
    asm volatile(
        "mma.sync.aligned.m16n8k8.row.col.f32.tf32.tf32.f32 "
        "{%0,%1,%2,%3}, {%4,%5,%6,%7}, {%8,%9}, {%0,%1,%2,%3};"
        : "+f"(d[0]), "+f"(d[1]), "+f"(d[2]), "+f"(d[3])
        : "r"(a[0]), "r"(a[1]), "r"(a[2]), "r"(a[3]), "r"(b[0]), "r"(b[1]));
}

// ================= tf32 tensor-core GEMM: C[M,N]=A[M,K]@B[K,N]+bias ==========
template<bool RELU>
__global__ __launch_bounds__(256)
void mmagemm(const float* __restrict__ A, const float* __restrict__ Bm,
             const float* __restrict__ bias, float* __restrict__ C,
             int M, int N, int K)
{
    extern __shared__ __align__(16) float sm[];
    float* As = sm;                 // [2][128][PA]
    float* Bs = sm + 2 * ABUF;      // [2][32][PB]

    const int tid  = threadIdx.x;
    const int lane = tid & 31;
    const int wid  = tid >> 5;
    const int wm   = (wid & 1) * 64;     // warp M offset in tile
    const int wn   = (wid >> 1) * 32;    // warp N offset in tile
    const int mb   = blockIdx.y * 128;
    const int nb   = blockIdx.x * 128;
    const int g    = lane >> 2;          // 0..7
    const int t    = lane & 3;           // 0..3

    float acc[4][4][4];
    #pragma unroll
    for (int i = 0; i < 4; i++)
        #pragma unroll
        for (int j = 0; j < 4; j++)
            #pragma unroll
            for (int r = 0; r < 4; r++) acc[i][j][r] = 0.f;

    // ---- async loaders ----
    const int arow  = tid >> 3;          // 0..31 (+32*i)
    const int acol  = (tid & 7) * 4;
    const int bk    = tid >> 5;          // 0..7 (+8*i)
    const int bcol  = (tid & 31) * 4;

#define LOAD_CHUNK(buf, kt)                                                        \
    {                                                                              \
        _Pragma("unroll")                                                          \
        for (int i = 0; i < 4; i++) {                                              \
            int row = arow + i * 32;                                               \
            const float* gp = A + (size_t)(mb + row) * K + (kt) + acol;            \
            uint32_t sa = smem_u32(As + (buf) * ABUF + row * PA + acol);           \
            int zf = (mb + row < M) ? 16 : 0;                                      \
            asm volatile("cp.async.cg.shared.global [%0], [%1], 16, %2;"           \
                         :: "r"(sa), "l"(gp), "r"(zf));                            \
        }                                                                          \
        _Pragma("unroll")                                                          \
        for (int i = 0; i < 4; i++) {                                              \
            int k = bk + i * 8;                                                    \
            const float* gp = Bm + (size_t)((kt) + k) * N + nb + bcol;             \
            uint32_t sa = smem_u32(Bs + (buf) * BBUF + k * PB + bcol);             \
            asm volatile("cp.async.cg.shared.global [%0], [%1], 16;"               \
                         :: "r"(sa), "l"(gp));                                     \
        }                                                                          \
        asm volatile("cp.async.commit_group;");                                    \
    }

    const int NIT = K >> 5;
    LOAD_CHUNK(0, 0);

    for (int it = 0; it < NIT; it++) {
        const int buf = it & 1;
        if (it + 1 < NIT) {
            LOAD_CHUNK(1 - buf, (it + 1) << 5);
            asm volatile("cp.async.wait_group 1;");
        } else {
            asm volatile("cp.async.wait_group 0;");
        }
        __syncthreads();

        const float* a_base = As + buf * ABUF;
        const float* b_base = Bs + buf * BBUF;
        #pragma unroll
        for (int k0 = 0; k0 < 32; k0 += 8) {
            uint32_t af[4][4];
            uint32_t bf[4][2];
            #pragma unroll
            for (int mt = 0; mt < 4; mt++) {
                const float* p = a_base + (wm + mt * 16 + g) * PA + k0 + t;
                af[mt][0] = __float_as_uint(p[0]);
                af[mt][1] = __float_as_uint(p[8 * PA]);
                af[mt][2] = __float_as_uint(p[4]);
                af[mt][3] = __float_as_uint(p[8 * PA + 4]);
            }
            #pragma unroll
            for (int nt = 0; nt < 4; nt++) {
                const float* p = b_base + (k0 + t) * PB + wn + nt * 8 + g;
                bf[nt][0] = __float_as_uint(p[0]);
                bf[nt][1] = __float_as_uint(p[4 * PB]);
            }
            #pragma unroll
            for (int mt = 0; mt < 4; mt++)
                #pragma unroll
                for (int nt = 0; nt < 4; nt++)
                    mma_tf32(acc[mt][nt], af[mt], bf[nt]);
        }
        __syncthreads();
    }
#undef LOAD_CHUNK

    // ---- epilogue ----
    #pragma unroll
    for (int mt = 0; mt < 4; mt++) {
        const int r0 = mb + wm + mt * 16 + g;
        const int r1 = r0 + 8;
        #pragma unroll
        for (int nt = 0; nt < 4; nt++) {
            const int c = nb + wn + nt * 8 + t * 2;
            const float b0 = __ldg(bias + c);
            const float b1 = __ldg(bias + c + 1);
            float v0 = acc[mt][nt][0] + b0;
            float v1 = acc[mt][nt][1] + b1;
            float v2 = acc[mt][nt][2] + b0;
            float v3 = acc[mt][nt][3] + b1;
            if (RELU) {
                v0 = fmaxf(v0, 0.f); v1 = fmaxf(v1, 0.f);
                v2 = fmaxf(v2, 0.f); v3 = fmaxf(v3, 0.f);
            }
            if (r0 < M) *(float2*)(C + (size_t)r0 * N + c) = make_float2(v0, v1);
            if (r1 < M) *(float2*)(C + (size_t)r1 * N + c) = make_float2(v2, v3);
        }
    }
}

// ---------------- elementwise add (q = src + pos) ----------------------------
__global__ void add_kernel(const float* __restrict__ a, const float* __restrict__ b,
                           float* __restrict__ o, int n4) {
    int i = blockIdx.x * blockDim.x + threadIdx.x;
    if (i < n4) {
        float4 x = ((const float4*)a)[i];
        float4 y = ((const float4*)b)[i];
        ((float4*)o)[i] = make_float4(x.x + y.x, x.y + y.y, x.z + y.z, x.w + y.w);
    }
}

// ---------------- deformable sampling: one warp per (b,s,h) ------------------
__global__ void sample_kernel(const float* __restrict__ value,
                              const float* __restrict__ offs,
                              const float* __restrict__ logits,
                              float* __restrict__ out) {
    int gw = (blockIdx.x * blockDim.x + threadIdx.x) >> 5;
    if (gw >= MT * HH) return;
    const int lane = threadIdx.x & 31;
    const int h  = gw & 7;
    const int bs = gw >> 3;
    const int s  = bs % SS;
    const int rowb = bs - s;

    float refx, refy;
    {
        int lvlH, lvlW, idx;
        if (s < 6400)      { lvlH = 80; lvlW = 80; idx = s; }
        else if (s < 8000) { lvlH = 40; lvlW = 40; idx = s - 6400; }
        else if (s < 8400) { lvlH = 20; lvlW = 20; idx = s - 8000; }
        else               { lvlH = 10; lvlW = 10; idx = s - 8400; }
        refx = ((idx % lvlW) + 0.5f) / (float)lvlW;
        refy = ((idx / lvlW) + 0.5f) / (float)lvlH;
    }

    const float* lg = logits + (size_t)gw * 16;
    float w[16];
    float mx = -1e30f;
    #pragma unroll
    for (int i = 0; i < 16; i++) { w[i] = __ldg(lg + i); mx = fmaxf(mx, w[i]); }
    float sum = 0.f;
    #pragma unroll
    for (int i = 0; i < 16; i++) { w[i] = __expf(w[i] - mx); sum += w[i]; }
    const float inv = 1.0f / sum;

    const float* of = offs + (size_t)gw * 32;
    const int d0 = h * DD + lane * 2;
    float ax = 0.f, ay = 0.f;

    const int LH[4] = {80, 40, 20, 10};
    const int LW[4] = {80, 40, 20, 10};
    const int LS[4] = {0, 6400, 8000, 8400};

    #pragma unroll
    for (int l = 0; l < 4; l++) {
        const int Hh = LH[l], Ww = LW[l];
        const float* vb = value + (size_t)(rowb + LS[l]) * CC + d0;
        #pragma unroll
        for (int p = 0; p < 4; p++) {
            float ox = __ldg(of + (l * 4 + p) * 2);
            float oy = __ldg(of + (l * 4 + p) * 2 + 1);
            float aw = w[l * 4 + p] * inv;
            float x = refx * (float)Ww + ox - 0.5f;
            float y = refy * (float)Hh + oy - 0.5f;
            float xf = floorf(x), yf = floorf(y);
            int x0 = (int)xf, y0 = (int)yf;
            float fx = x - xf, fy = y - yf;
            float w00 = (1.f - fx) * (1.f - fy) * aw;
            float w01 = fx * (1.f - fy) * aw;
            float w10 = (1.f - fx) * fy * aw;
            float w11 = fx * fy * aw;
            bool xi0 = (x0 >= 0) && (x0 < Ww);
            bool xi1 = (x0 + 1 >= 0) && (x0 + 1 < Ww);
            bool yi0 = (y0 >= 0) && (y0 < Hh);
            bool yi1 = (y0 + 1 >= 0) && (y0 + 1 < Hh);
            if (xi0 && yi0) {
                float2 v = *(const float2*)(vb + (size_t)(y0 * Ww + x0) * CC);
                ax += w00 * v.x; ay += w00 * v.y;
            }
            if (xi1 && yi0) {
                float2 v = *(const float2*)(vb + (size_t)(y0 * Ww + x0 + 1) * CC);
                ax += w01 * v.x; ay += w01 * v.y;
            }
            if (xi0 && yi1) {
                float2 v = *(const float2*)(vb + (size_t)((y0 + 1) * Ww + x0) * CC);
                ax += w10 * v.x; ay += w10 * v.y;
            }
            if (xi1 && yi1) {
                float2 v = *(const float2*)(vb + (size_t)((y0 + 1) * Ww + x0 + 1) * CC);
                ax += w11 * v.x; ay += w11 * v.y;
            }
        }
    }
    *(float2*)(out + (size_t)bs * CC + d0) = make_float2(ax, ay);
}

// ---------------- fused residual + LayerNorm ---------------------------------
__global__ void ln_residual(const float* __restrict__ a, const float* __restrict__ r,
                            const float* __restrict__ g, const float* __restrict__ bta,
                            float* __restrict__ out) {
    const int row = blockIdx.x;
    const int t = threadIdx.x;
    const float4 va = ((const float4*)(a + (size_t)row * CC))[t];
    const float4 vr = ((const float4*)(r + (size_t)row * CC))[t];
    float x0 = va.x + vr.x, x1 = va.y + vr.y, x2 = va.z + vr.z, x3 = va.w + vr.w;

    float sum = x0 + x1 + x2 + x3;
    float sq  = x0 * x0 + x1 * x1 + x2 * x2 + x3 * x3;
    #pragma unroll
    for (int o = 16; o; o >>= 1) {
        sum += __shfl_xor_sync(0xffffffffu, sum, o);
        sq  += __shfl_xor_sync(0xffffffffu, sq,  o);
    }
    __shared__ float sh[8];
    const int wid = t >> 5, lane = t & 31;
    if (lane == 0) { sh[wid] = sum; sh[wid + 4] = sq; }
    __syncthreads();
    sum = sh[0] + sh[1] + sh[2] + sh[3];
    sq  = sh[4] + sh[5] + sh[6] + sh[7];

    const float mean = sum * (1.0f / CC);
    const float var  = sq * (1.0f / CC) - mean * mean;
    const float istd = rsqrtf(var + 1e-5f);

    const float4 vg = ((const float4*)g)[t];
    const float4 vb = ((const float4*)bta)[t];
    float4 o4;
    o4.x = (x0 - mean) * istd * vg.x + vb.x;
    o4.y = (x1 - mean) * istd * vg.y + vb.y;
    o4.z = (x2 - mean) * istd * vg.z + vb.z;
    o4.w = (x3 - mean) * istd * vg.w + vb.w;
    ((float4*)(out + (size_t)row * CC))[t] = o4;
}

// ---------------- launch ------------------------------------------------------
static float* sym(const void* s) {
    void* p = nullptr;
    cudaGetSymbolAddress(&p, s);
    return (float*)p;
}

extern "C" void kernel_launch(void* const* d_in, const int* in_sizes, int n_in,
                              void* d_out, int out_size) {
    const float* src    = (const float*)d_in[0];
    const float* pos    = (const float*)d_in[1];
    const float* w_off  = (const float*)d_in[2];
    const float* b_off  = (const float*)d_in[3];
    const float* w_attn = (const float*)d_in[4];
    const float* b_attn = (const float*)d_in[5];
    const float* w_val  = (const float*)d_in[6];
    const float* b_val  = (const float*)d_in[7];
    const float* w_out  = (const float*)d_in[8];
    const float* b_out  = (const float*)d_in[9];
    const float* ln1_g  = (const float*)d_in[10];
    const float* ln1_b  = (const float*)d_in[11];
    const float* w1     = (const float*)d_in[12];
    const float* b1     = (const float*)d_in[13];
    const float* w2     = (const float*)d_in[14];
    const float* b2     = (const float*)d_in[15];
    const float* ln2_g  = (const float*)d_in[16];
    const float* ln2_b  = (const float*)d_in[17];
    float* out = (float*)d_out;

    float* q    = sym(g_q);
    float* val  = sym(g_val);
    float* off  = sym(g_off);
    float* lgt  = sym(g_lgt);
    float* smp  = sym(g_smp);
    float* tmp  = sym(g_tmp);
    float* x    = sym(g_x);
    float* hid  = sym(g_hid);

    const int SMEM_SZ = SMEM_FLOATS * 4;   // ~70KB
    cudaFuncSetAttribute(mmagemm<false>, cudaFuncAttributeMaxDynamicSharedMemorySize, SMEM_SZ);
    cudaFuncSetAttribute(mmagemm<true>,  cudaFuncAttributeMaxDynamicSharedMemorySize, SMEM_SZ);

    const int mblocks = (MT + 127) / 128;   // 133

    // 1. q = src + pos
    {
        int n4 = MT * CC / 4;
        add_kernel<<<(n4 + 255) / 256, 256>>>(src, pos, q, n4);
    }
    // 2. value = src @ w_val + b_val
    mmagemm<false><<<dim3(CC / 128, mblocks), 256, SMEM_SZ>>>(src, w_val, b_val, val, MT, CC, CC);
    // 3. offsets = q @ w_off + b_off
    mmagemm<false><<<dim3(256 / 128, mblocks), 256, SMEM_SZ>>>(q, w_off, b_off, off, MT, 256, CC);
    // 4. logits = q @ w_attn + b_attn
    mmagemm<false><<<dim3(1, mblocks), 256, SMEM_SZ>>>(q, w_attn, b_attn, lgt, MT, 128, CC);
    // 5. deformable sampling
    {
        int warps = MT * HH;
        int blocks = (warps * 32 + 255) / 256;
        sample_kernel<<<blocks, 256>>>(val, off, lgt, smp);
    }
    // 6. attn_out = smp @ w_out + b_out
    mmagemm<false><<<dim3(CC / 128, mblocks), 256, SMEM_SZ>>>(smp, w_out, b_out, tmp, MT, CC, CC);
    // 7. x = LN(src + attn_out)
    ln_residual<<<MT, 128>>>(src, tmp, ln1_g, ln1_b, x);
    // 8. hid = relu(x @ w1 + b1)
    mmagemm<true><<<dim3(DFFN / 128, mblocks), 256, SMEM_SZ>>>(x, w1, b1, hid, MT, DFFN, CC);
    // 9. ffn = hid @ w2 + b2
    mmagemm<false><<<dim3(CC / 128, mblocks), 256, SMEM_SZ>>>(hid, w2, b2, tmp, MT, CC, DFFN);
    // 10. out = LN(x + ffn)
    ln_residual<<<MT, 128>>>(x, tmp, ln2_g, ln2_b, out);
}